// round 2
// baseline (speedup 1.0000x reference)
#include <cuda_runtime.h>

#define NROWS 32768
#define DIM   64
#define KC    1024
#define KT    128
#define THREADS 256
#define NBLOCKS (NROWS / THREADS)   // 128

typedef unsigned long long u64;
typedef unsigned int u32;

// Scratch (device globals: allocation-free)
__device__ u32   g_colmin[KC];
__device__ float g_cnorm[KC];
__device__ float g_mse[NBLOCKS];

// Monotone float <-> uint encoding (so atomicMin.u32 == float min, incl. negatives)
__device__ __forceinline__ u32 fenc(float f) {
    u32 u = __float_as_uint(f);
    return u ^ (((u32)((int)u >> 31)) | 0x80000000u);
}
__device__ __forceinline__ float fdec(u32 e) {
    u32 u = (e & 0x80000000u) ? (e ^ 0x80000000u) : ~e;
    return __uint_as_float(u);
}

// ---------------------------------------------------------------------------
// Kernel 0: codebook norms + reset column-min (must reset EVERY call: graph replays)
// ---------------------------------------------------------------------------
__global__ void vq_init(const float* __restrict__ cb) {
    int k = threadIdx.x;   // 1024 threads
    float s = 0.f;
    const float4* cp = reinterpret_cast<const float4*>(cb + (size_t)k * DIM);
#pragma unroll
    for (int i = 0; i < DIM / 4; i++) {
        float4 c = cp[i];
        s += c.x * c.x + c.y * c.y + c.z * c.z + c.w * c.w;
    }
    g_cnorm[k]  = s;
    g_colmin[k] = 0xFFFFFFFFu;
}

// ---------------------------------------------------------------------------
// Kernel 1: main — argmin per row, column-min per code, MSE partials, output
// ---------------------------------------------------------------------------
__global__ __launch_bounds__(THREADS) void vq_main(
    const float* __restrict__ x,
    const float* __restrict__ cb,
    float* __restrict__ out)
{
    __shared__ float sc[KT * DIM];     // 32 KB codebook tile
    __shared__ float scn[KT];          // tile norms
    __shared__ float smse[THREADS / 32];

    const int row = blockIdx.x * THREADS + threadIdx.x;

    // Load this thread's x row; compute ||x||^2; pack to f32x2 operands.
    u64 xv[DIM / 2];
    float xnorm = 0.f;
    {
        const float4* xp = reinterpret_cast<const float4*>(x + (size_t)row * DIM);
#pragma unroll
        for (int i = 0; i < DIM / 4; i++) {
            float4 v = xp[i];
            xnorm += v.x * v.x + v.y * v.y + v.z * v.z + v.w * v.w;
            asm("mov.b64 %0,{%1,%2};" : "=l"(xv[2 * i])     : "f"(v.x), "f"(v.y));
            asm("mov.b64 %0,{%1,%2};" : "=l"(xv[2 * i + 1]) : "f"(v.z), "f"(v.w));
        }
    }

    float best  = 3.4e38f;
    int   bestk = 0;

    for (int kt = 0; kt < KC; kt += KT) {
        __syncthreads();
        // Cooperative tile load: KT*DIM floats = 2048 float4 / 256 threads = 8 each
        {
            const float4* cg = reinterpret_cast<const float4*>(cb + (size_t)kt * DIM);
            float4* s4 = reinterpret_cast<float4*>(sc);
#pragma unroll
            for (int i = 0; i < (KT * DIM / 4) / THREADS; i++)
                s4[threadIdx.x + i * THREADS] = cg[threadIdx.x + i * THREADS];
            if (threadIdx.x < KT) scn[threadIdx.x] = g_cnorm[kt + threadIdx.x];
        }
        __syncthreads();

#pragma unroll 2
        for (int kk = 0; kk < KT; kk++) {
            const u64* c2 = reinterpret_cast<const u64*>(sc + kk * DIM);
            u64 a0 = 0ull, a1 = 0ull, a2 = 0ull, a3 = 0ull;  // (0.f,0.f) packed
#pragma unroll
            for (int j = 0; j < DIM / 2; j += 4) {
                asm("fma.rn.f32x2 %0,%1,%2,%0;" : "+l"(a0) : "l"(xv[j]),     "l"(c2[j]));
                asm("fma.rn.f32x2 %0,%1,%2,%0;" : "+l"(a1) : "l"(xv[j + 1]), "l"(c2[j + 1]));
                asm("fma.rn.f32x2 %0,%1,%2,%0;" : "+l"(a2) : "l"(xv[j + 2]), "l"(c2[j + 2]));
                asm("fma.rn.f32x2 %0,%1,%2,%0;" : "+l"(a3) : "l"(xv[j + 3]), "l"(c2[j + 3]));
            }
            float l0, h0, l1, h1, l2, h2, l3, h3;
            asm("mov.b64 {%0,%1},%2;" : "=f"(l0), "=f"(h0) : "l"(a0));
            asm("mov.b64 {%0,%1},%2;" : "=f"(l1), "=f"(h1) : "l"(a1));
            asm("mov.b64 {%0,%1},%2;" : "=f"(l2), "=f"(h2) : "l"(a2));
            asm("mov.b64 {%0,%1},%2;" : "=f"(l3), "=f"(h3) : "l"(a3));
            float dot  = ((l0 + h0) + (l1 + h1)) + ((l2 + h2) + (l3 + h3));
            // match reference order: (||x||^2 - 2 x.c) + ||c||^2
            float dist = (xnorm - 2.f * dot) + scn[kk];
            int   kg   = kt + kk;
            if (dist < best) { best = dist; bestk = kg; }  // first-index tie-break
            // column-min over the warp's 32 rows, then one RED.global.min per warp
            u32 m = __reduce_min_sync(0xFFFFFFFFu, fenc(dist));
            if ((threadIdx.x & 31) == 0) atomicMin(&g_colmin[kg], m);
        }
    }

    // Epilogue: emb = cb[bestk]; out = x + (c - x) (exact reference rounding); MSE
    float mse = 0.f;
    {
        const float2* cbest = reinterpret_cast<const float2*>(cb + (size_t)bestk * DIM);
        float2* op = reinterpret_cast<float2*>(out + (size_t)row * DIM);
#pragma unroll
        for (int i = 0; i < DIM / 2; i++) {
            float xlo, xhi;
            asm("mov.b64 {%0,%1},%2;" : "=f"(xlo), "=f"(xhi) : "l"(xv[i]));
            float2 c = cbest[i];
            float dlo = c.x - xlo;
            float dhi = c.y - xhi;
            mse += dlo * dlo + dhi * dhi;
            float2 o;
            o.x = xlo + dlo;
            o.y = xhi + dhi;
            op[i] = o;
        }
    }
    // Deterministic block reduction of MSE -> per-block partial
#pragma unroll
    for (int o = 16; o > 0; o >>= 1)
        mse += __shfl_down_sync(0xFFFFFFFFu, mse, o);
    if ((threadIdx.x & 31) == 0) smse[threadIdx.x >> 5] = mse;
    __syncthreads();
    if (threadIdx.x == 0) {
        float s = 0.f;
#pragma unroll
        for (int i = 0; i < THREADS / 32; i++) s += smse[i];
        g_mse[blockIdx.x] = s;
    }
}

// ---------------------------------------------------------------------------
// Kernel 2: combine -> loss scalar
// ---------------------------------------------------------------------------
__global__ void vq_final(float* __restrict__ out, int out_size) {
    __shared__ float sw[32];
    int t = threadIdx.x;               // 1024 threads
    float v = fdec(g_colmin[t]);
#pragma unroll
    for (int o = 16; o > 0; o >>= 1)
        v += __shfl_down_sync(0xFFFFFFFFu, v, o);
    if ((t & 31) == 0) sw[t >> 5] = v;
    __syncthreads();
    if (t == 0) {
        float ent = 0.f;
#pragma unroll
        for (int i = 0; i < 32; i++) ent += sw[i];
        float ms = 0.f;
        for (int i = 0; i < NBLOCKS; i++) ms += g_mse[i];
        float m = ms / (float)((size_t)NROWS * DIM);
        // emb_loss(1.0) + commit_loss(0.25) + entropy(0.1), reference add order
        float loss = (m + 0.25f * m) + 0.1f * (ent / (float)KC);
        if (out_size > NROWS * DIM) out[out_size - 1] = loss;
    }
}

// ---------------------------------------------------------------------------
extern "C" void kernel_launch(void* const* d_in, const int* in_sizes, int n_in,
                              void* d_out, int out_size) {
    const float* x  = (const float*)d_in[0];
    const float* cb = (const float*)d_in[1];
    // Defensive: identify which input is the codebook by element count
    if (n_in >= 2 && in_sizes[0] == KC * DIM && in_sizes[1] == NROWS * DIM) {
        const float* t = x; x = cb; cb = t;
    }
    float* out = (float*)d_out;

    vq_init<<<1, KC>>>(cb);
    vq_main<<<NBLOCKS, THREADS>>>(x, cb, out);
    vq_final<<<1, KC>>>(out, out_size);
}